// round 1
// baseline (speedup 1.0000x reference)
#include <cuda_runtime.h>
#include <math.h>

// ---------------- device-global scratch (no allocs allowed) ----------------
__device__ float  g_w0q[320];      // 5x64 quantized
__device__ float  g_wq[3][4096];   // w1,w2,w3 quantized (64x64 row-major [k][j])
__device__ float  g_w4q[64];       // 64x1 quantized
__device__ float  g_b0q[64];
__device__ float  g_bq[3][64];
__device__ float  g_b4q[1];
__device__ float4 g_grid0[128];
__device__ float4 g_grid1[512];
__device__ float4 g_grid2[2048];

// ---------------- prep 1: weight quantization -------------------------------
// Q_LEVELS = 8**2 - 1 = 63 (per reference, NOT 2**8-1)
__global__ void quant_kernel(const float* w0, const float* w1, const float* w2,
                             const float* w3, const float* w4,
                             const float* b0, const float* b1, const float* b2,
                             const float* b3, const float* b4)
{
    __shared__ float smin[256], smax[256];
    const float* src; float* dst; int n;
    switch (blockIdx.x) {
        case 0: src = w0; dst = g_w0q;   n = 320;  break;
        case 1: src = w1; dst = g_wq[0]; n = 4096; break;
        case 2: src = w2; dst = g_wq[1]; n = 4096; break;
        case 3: src = w3; dst = g_wq[2]; n = 4096; break;
        case 4: src = w4; dst = g_w4q;   n = 64;   break;
        case 5: src = b0; dst = g_b0q;   n = 64;   break;
        case 6: src = b1; dst = g_bq[0]; n = 64;   break;
        case 7: src = b2; dst = g_bq[1]; n = 64;   break;
        case 8: src = b3; dst = g_bq[2]; n = 64;   break;
        default: src = b4; dst = g_b4q;  n = 1;    break;
    }
    int t = threadIdx.x;
    float mn = INFINITY, mx = -INFINITY;
    for (int i = t; i < n; i += 256) {
        float v = src[i];
        mn = fminf(mn, v); mx = fmaxf(mx, v);
    }
    smin[t] = mn; smax[t] = mx;
    __syncthreads();
    for (int s = 128; s > 0; s >>= 1) {
        if (t < s) {
            smin[t] = fminf(smin[t], smin[t + s]);
            smax[t] = fmaxf(smax[t], smax[t + s]);
        }
        __syncthreads();
    }
    mn = smin[0]; mx = smax[0];
    float scale = fmaxf(mx - mn, 1e-8f) / 63.0f;
    for (int i = t; i < n; i += 256) {
        // jnp.round is round-half-even -> rintf
        dst[i] = rintf((src[i] - mn) / scale) * scale + mn;
    }
}

// ---------------- prep 2: grid tables (STE forward == argmax gather) --------
__global__ void grid_kernel(const float* ind0, const float* cb0,
                            const float* ind1, const float* cb1,
                            const float* ind2, const float* cb2)
{
    int idx = blockIdx.x * blockDim.x + threadIdx.x;
    const float* ind; const float* cb; float4* dst; int row;
    if (idx < 128)       { ind = ind0; cb = cb0; dst = g_grid0; row = idx; }
    else if (idx < 640)  { ind = ind1; cb = cb1; dst = g_grid1; row = idx - 128; }
    else if (idx < 2688) { ind = ind2; cb = cb2; dst = g_grid2; row = idx - 640; }
    else return;
    const float* r = ind + (long)row * 64;
    float best = r[0]; int arg = 0;
    #pragma unroll
    for (int j = 1; j < 64; j++) {
        float v = r[j];
        if (v > best) { best = v; arg = j; }   // strict > == first-occurrence tie-break
    }
    dst[row] = make_float4(cb[arg * 4 + 0], cb[arg * 4 + 1],
                           cb[arg * 4 + 2], cb[arg * 4 + 3]);
}

// ---------------- main fused kernel -----------------------------------------
__device__ __forceinline__ float gelu_exact(float v) {
    return 0.5f * v * (1.0f + erff(v * 0.7071067811865475f));
}

__global__ void __launch_bounds__(256)
mlp_kernel(const float* __restrict__ x, float* __restrict__ out, int N)
{
    __shared__ float ws[3][4096];   // exactly 48KB: w1,w2,w3
    for (int i = threadIdx.x; i < 4096; i += 256) {
        ws[0][i] = g_wq[0][i];
        ws[1][i] = g_wq[1][i];
        ws[2][i] = g_wq[2][i];
    }
    __syncthreads();

    int idx = blockIdx.x * blockDim.x + threadIdx.x;
    if (idx >= N) return;

    float2 xv = ((const float2*)x)[idx];
    float feat = xv.x;                  // x[:, 0]
    float t = (xv.y + 1.0f) * 0.5f;     // coord = x[:, 1], mapped to [0,1]

    float4 g = make_float4(0.f, 0.f, 0.f, 0.f);

    auto interp_add = [&](const float4* __restrict__ tab, int res) {
        float c = t * (float)(res - 1);
        int left  = min((int)floorf(c), res - 2);
        int right = max((int)ceilf(c), 1);
        float w = c - (float)left;
        float4 gl = __ldg(tab + left);
        float4 gr = __ldg(tab + right);
        g.x += (1.0f - w) * gl.x + w * gr.x;
        g.y += (1.0f - w) * gl.y + w * gr.y;
        g.z += (1.0f - w) * gl.z + w * gr.z;
        g.w += (1.0f - w) * gl.w + w * gr.w;
    };
    interp_add(g_grid0, 128);
    interp_add(g_grid1, 512);
    interp_add(g_grid2, 2048);

    float in5[5] = { g.x, g.y, g.z, g.w, feat };
    float h[64];

    // ---- layer 0: 5 -> 64 (small weights read via L1/L2) ----
    #pragma unroll
    for (int jv = 0; jv < 16; jv++) {
        float4 acc = __ldg(((const float4*)g_b0q) + jv);
        #pragma unroll
        for (int k = 0; k < 5; k++) {
            float4 wv = __ldg(((const float4*)(g_w0q + k * 64)) + jv);
            acc.x = fmaf(in5[k], wv.x, acc.x);
            acc.y = fmaf(in5[k], wv.y, acc.y);
            acc.z = fmaf(in5[k], wv.z, acc.z);
            acc.w = fmaf(in5[k], wv.w, acc.w);
        }
        h[4 * jv + 0] = acc.x; h[4 * jv + 1] = acc.y;
        h[4 * jv + 2] = acc.z; h[4 * jv + 3] = acc.w;
    }

    // ---- layers 1..3: gelu -> 64x64 (weights in smem, broadcast LDS) ----
    #pragma unroll 1
    for (int l = 0; l < 3; l++) {
        #pragma unroll
        for (int k = 0; k < 64; k++) h[k] = gelu_exact(h[k]);

        float acc[64];
        #pragma unroll
        for (int jv = 0; jv < 16; jv++) {
            float4 b = __ldg(((const float4*)g_bq[l]) + jv);
            acc[4 * jv + 0] = b.x; acc[4 * jv + 1] = b.y;
            acc[4 * jv + 2] = b.z; acc[4 * jv + 3] = b.w;
        }
        const float* wl = ws[l];
        #pragma unroll
        for (int k = 0; k < 64; k++) {
            float a = h[k];
            const float4* row = (const float4*)(wl + k * 64);
            #pragma unroll
            for (int jv = 0; jv < 16; jv++) {
                float4 wv = row[jv];
                acc[4 * jv + 0] = fmaf(a, wv.x, acc[4 * jv + 0]);
                acc[4 * jv + 1] = fmaf(a, wv.y, acc[4 * jv + 1]);
                acc[4 * jv + 2] = fmaf(a, wv.z, acc[4 * jv + 2]);
                acc[4 * jv + 3] = fmaf(a, wv.w, acc[4 * jv + 3]);
            }
        }
        #pragma unroll
        for (int k = 0; k < 64; k++) h[k] = acc[k];
    }

    // ---- final: gelu -> 64x1 -> tanh ----
    float v = __ldg(g_b4q);
    #pragma unroll
    for (int k = 0; k < 64; k++)
        v = fmaf(gelu_exact(h[k]), __ldg(g_w4q + k), v);

    out[idx] = tanhf(v);
}

// ---------------- launch ----------------
extern "C" void kernel_launch(void* const* d_in, const int* in_sizes, int n_in,
                              void* d_out, int out_size)
{
    const float* x    = (const float*)d_in[0];
    const float* cb0  = (const float*)d_in[1];
    const float* ind0 = (const float*)d_in[2];
    const float* cb1  = (const float*)d_in[3];
    const float* ind1 = (const float*)d_in[4];
    const float* cb2  = (const float*)d_in[5];
    const float* ind2 = (const float*)d_in[6];
    const float* w0   = (const float*)d_in[7];
    const float* b0   = (const float*)d_in[8];
    const float* w1   = (const float*)d_in[9];
    const float* b1   = (const float*)d_in[10];
    const float* w2   = (const float*)d_in[11];
    const float* b2   = (const float*)d_in[12];
    const float* w3   = (const float*)d_in[13];
    const float* b3   = (const float*)d_in[14];
    const float* w4   = (const float*)d_in[15];
    const float* b4   = (const float*)d_in[16];

    int N = in_sizes[0] / 2;

    quant_kernel<<<10, 256>>>(w0, w1, w2, w3, w4, b0, b1, b2, b3, b4);
    grid_kernel<<<(2688 + 255) / 256, 256>>>(ind0, cb0, ind1, cb1, ind2, cb2);
    mlp_kernel<<<(N + 255) / 256, 256>>>(x, (float*)d_out, N);
}

// round 2
// speedup vs baseline: 1.3190x; 1.3190x over previous
#include <cuda_runtime.h>
#include <math.h>

// ---------------- device-global scratch (no allocs allowed) ----------------
__device__ __align__(16) float  g_w0q[320];      // 5x64 quantized
__device__ __align__(16) float  g_wq[3][4096];   // w1,w2,w3 quantized ([k][j])
__device__ __align__(16) float  g_w4q[64];       // 64x1 quantized
__device__ __align__(16) float  g_b0q[64];
__device__ __align__(16) float  g_bq[3][64];
__device__ __align__(16) float  g_b4q[4];        // only [0] used
__device__ float4 g_grid0[128];
__device__ float4 g_grid1[512];
__device__ float4 g_grid2[2048];

// ---------------- f32x2 packed helpers (Blackwell FFMA2 pipe) --------------
__device__ __forceinline__ unsigned long long pack2(float lo, float hi) {
    unsigned long long r;
    asm("mov.b64 %0, {%1, %2};" : "=l"(r) : "f"(lo), "f"(hi));
    return r;
}
__device__ __forceinline__ void unpack2(unsigned long long v, float& lo, float& hi) {
    asm("mov.b64 {%0, %1}, %2;" : "=f"(lo), "=f"(hi) : "l"(v));
}
__device__ __forceinline__ unsigned long long fma2(unsigned long long a,
                                                   unsigned long long b,
                                                   unsigned long long c) {
    unsigned long long d;
    asm("fma.rn.f32x2 %0, %1, %2, %3;" : "=l"(d) : "l"(a), "l"(b), "l"(c));
    return d;
}

// ---------------- prep 1: weight quantization -------------------------------
// Q_LEVELS = 8**2 - 1 = 63 (per reference, NOT 2**8-1)
__global__ void quant_kernel(const float* w0, const float* w1, const float* w2,
                             const float* w3, const float* w4,
                             const float* b0, const float* b1, const float* b2,
                             const float* b3, const float* b4)
{
    __shared__ float smin[256], smax[256];
    const float* src; float* dst; int n;
    switch (blockIdx.x) {
        case 0: src = w0; dst = g_w0q;   n = 320;  break;
        case 1: src = w1; dst = g_wq[0]; n = 4096; break;
        case 2: src = w2; dst = g_wq[1]; n = 4096; break;
        case 3: src = w3; dst = g_wq[2]; n = 4096; break;
        case 4: src = w4; dst = g_w4q;   n = 64;   break;
        case 5: src = b0; dst = g_b0q;   n = 64;   break;
        case 6: src = b1; dst = g_bq[0]; n = 64;   break;
        case 7: src = b2; dst = g_bq[1]; n = 64;   break;
        case 8: src = b3; dst = g_bq[2]; n = 64;   break;
        default: src = b4; dst = g_b4q;  n = 1;    break;
    }
    int t = threadIdx.x;
    float mn = INFINITY, mx = -INFINITY;
    for (int i = t; i < n; i += 256) {
        float v = src[i];
        mn = fminf(mn, v); mx = fmaxf(mx, v);
    }
    smin[t] = mn; smax[t] = mx;
    __syncthreads();
    for (int s = 128; s > 0; s >>= 1) {
        if (t < s) {
            smin[t] = fminf(smin[t], smin[t + s]);
            smax[t] = fmaxf(smax[t], smax[t + s]);
        }
        __syncthreads();
    }
    mn = smin[0]; mx = smax[0];
    float scale = fmaxf(mx - mn, 1e-8f) / 63.0f;
    for (int i = t; i < n; i += 256) {
        // jnp.round is round-half-even -> rintf
        dst[i] = rintf((src[i] - mn) / scale) * scale + mn;
    }
}

// ---------------- prep 2: grid tables (STE forward == argmax gather) --------
__global__ void grid_kernel(const float* ind0, const float* cb0,
                            const float* ind1, const float* cb1,
                            const float* ind2, const float* cb2)
{
    int idx = blockIdx.x * blockDim.x + threadIdx.x;
    const float* ind; const float* cb; float4* dst; int row;
    if (idx < 128)       { ind = ind0; cb = cb0; dst = g_grid0; row = idx; }
    else if (idx < 640)  { ind = ind1; cb = cb1; dst = g_grid1; row = idx - 128; }
    else if (idx < 2688) { ind = ind2; cb = cb2; dst = g_grid2; row = idx - 640; }
    else return;
    const float* r = ind + (long)row * 64;
    float best = r[0]; int arg = 0;
    #pragma unroll
    for (int j = 1; j < 64; j++) {
        float v = r[j];
        if (v > best) { best = v; arg = j; }   // strict > == first-occurrence tie-break
    }
    dst[row] = make_float4(cb[arg * 4 + 0], cb[arg * 4 + 1],
                           cb[arg * 4 + 2], cb[arg * 4 + 3]);
}

// ---------------- gelu on a packed pair (erff stays exact) ------------------
__device__ __forceinline__ unsigned long long gelu2(unsigned long long v2) {
    float a, b;
    unpack2(v2, a, b);
    float ga = 0.5f * a * (1.0f + erff(a * 0.70710678118654752f));
    float gb = 0.5f * b * (1.0f + erff(b * 0.70710678118654752f));
    return pack2(ga, gb);
}

// ---------------- main fused kernel -----------------------------------------
__global__ void __launch_bounds__(256)
mlp_kernel(const float* __restrict__ x, float* __restrict__ out, int N)
{
    __shared__ __align__(16) float ws[3][4096];   // 48KB: w1,w2,w3
    for (int i = threadIdx.x; i < 4096; i += 256) {
        ws[0][i] = g_wq[0][i];
        ws[1][i] = g_wq[1][i];
        ws[2][i] = g_wq[2][i];
    }
    __syncthreads();

    int idx = blockIdx.x * blockDim.x + threadIdx.x;
    if (idx >= N) return;

    float2 xv = ((const float2*)x)[idx];
    float feat = xv.x;                  // x[:, 0]
    float t = (xv.y + 1.0f) * 0.5f;     // coord = x[:, 1], mapped to [0,1]

    float4 g = make_float4(0.f, 0.f, 0.f, 0.f);

    auto interp_add = [&](const float4* __restrict__ tab, int res) {
        float c = t * (float)(res - 1);
        int left  = min((int)floorf(c), res - 2);
        int right = max((int)ceilf(c), 1);
        float w = c - (float)left;
        float4 gl = __ldg(tab + left);
        float4 gr = __ldg(tab + right);
        g.x += (1.0f - w) * gl.x + w * gr.x;
        g.y += (1.0f - w) * gl.y + w * gr.y;
        g.z += (1.0f - w) * gl.z + w * gr.z;
        g.w += (1.0f - w) * gl.w + w * gr.w;
    };
    interp_add(g_grid0, 128);
    interp_add(g_grid1, 512);
    interp_add(g_grid2, 2048);

    float in5[5] = { g.x, g.y, g.z, g.w, feat };

    unsigned long long h2[32];   // 64 activations as 32 packed f32x2

    // ---- layer 0: 5 -> 64 (packed) ----
    {
        const ulonglong2* bp = (const ulonglong2*)g_b0q;
        #pragma unroll
        for (int j = 0; j < 16; j++) {
            ulonglong2 b = __ldg(bp + j);
            h2[2 * j] = b.x; h2[2 * j + 1] = b.y;
        }
        #pragma unroll
        for (int k = 0; k < 5; k++) {
            unsigned long long aa = pack2(in5[k], in5[k]);
            const ulonglong2* row = (const ulonglong2*)(g_w0q + k * 64);
            #pragma unroll
            for (int j = 0; j < 16; j++) {
                ulonglong2 wv = __ldg(row + j);
                h2[2 * j]     = fma2(aa, wv.x, h2[2 * j]);
                h2[2 * j + 1] = fma2(aa, wv.y, h2[2 * j + 1]);
            }
        }
    }

    // ---- layers 1..3: gelu -> 64x64 (smem weights, FFMA2) ----
    #pragma unroll 1
    for (int l = 0; l < 3; l++) {
        #pragma unroll
        for (int j = 0; j < 32; j++) h2[j] = gelu2(h2[j]);

        unsigned long long acc2[32];
        const ulonglong2* bp = (const ulonglong2*)g_bq[l];
        #pragma unroll
        for (int j = 0; j < 16; j++) {
            ulonglong2 b = __ldg(bp + j);
            acc2[2 * j] = b.x; acc2[2 * j + 1] = b.y;
        }

        const float* wl = ws[l];
        #pragma unroll
        for (int kp = 0; kp < 32; kp++) {
            float a0, a1;
            unpack2(h2[kp], a0, a1);
            unsigned long long aa0 = pack2(a0, a0);
            unsigned long long aa1 = pack2(a1, a1);
            const ulonglong2* row0 = (const ulonglong2*)(wl + (2 * kp) * 64);
            const ulonglong2* row1 = (const ulonglong2*)(wl + (2 * kp + 1) * 64);
            #pragma unroll
            for (int j = 0; j < 16; j++) {
                ulonglong2 w0v = row0[j];
                acc2[2 * j]     = fma2(aa0, w0v.x, acc2[2 * j]);
                acc2[2 * j + 1] = fma2(aa0, w0v.y, acc2[2 * j + 1]);
            }
            #pragma unroll
            for (int j = 0; j < 16; j++) {
                ulonglong2 w1v = row1[j];
                acc2[2 * j]     = fma2(aa1, w1v.x, acc2[2 * j]);
                acc2[2 * j + 1] = fma2(aa1, w1v.y, acc2[2 * j + 1]);
            }
        }
        #pragma unroll
        for (int j = 0; j < 32; j++) h2[j] = acc2[j];
    }

    // ---- final: gelu -> 64x1 -> tanh (packed dot) ----
    {
        unsigned long long v2 = pack2(__ldg(g_b4q), 0.0f);
        const ulonglong2* w4p = (const ulonglong2*)g_w4q;
        #pragma unroll
        for (int j = 0; j < 16; j++) {
            ulonglong2 wv = __ldg(w4p + j);
            v2 = fma2(gelu2(h2[2 * j]),     wv.x, v2);
            v2 = fma2(gelu2(h2[2 * j + 1]), wv.y, v2);
        }
        float vlo, vhi;
        unpack2(v2, vlo, vhi);
        out[idx] = tanhf(vlo + vhi);
    }
}

// ---------------- launch ----------------
extern "C" void kernel_launch(void* const* d_in, const int* in_sizes, int n_in,
                              void* d_out, int out_size)
{
    const float* x    = (const float*)d_in[0];
    const float* cb0  = (const float*)d_in[1];
    const float* ind0 = (const float*)d_in[2];
    const float* cb1  = (const float*)d_in[3];
    const float* ind1 = (const float*)d_in[4];
    const float* cb2  = (const float*)d_in[5];
    const float* ind2 = (const float*)d_in[6];
    const float* w0   = (const float*)d_in[7];
    const float* b0   = (const float*)d_in[8];
    const float* w1   = (const float*)d_in[9];
    const float* b1   = (const float*)d_in[10];
    const float* w2   = (const float*)d_in[11];
    const float* b2   = (const float*)d_in[12];
    const float* w3   = (const float*)d_in[13];
    const float* b3   = (const float*)d_in[14];
    const float* w4   = (const float*)d_in[15];
    const float* b4   = (const float*)d_in[16];

    int N = in_sizes[0] / 2;

    quant_kernel<<<10, 256>>>(w0, w1, w2, w3, w4, b0, b1, b2, b3, b4);
    grid_kernel<<<(2688 + 255) / 256, 256>>>(ind0, cb0, ind1, cb1, ind2, cb2);
    mlp_kernel<<<(N + 255) / 256, 256>>>(x, (float*)d_out, N);
}

// round 3
// speedup vs baseline: 1.8709x; 1.4185x over previous
#include <cuda_runtime.h>
#include <math.h>

// ---------------- device-global scratch (no allocs allowed) ----------------
__device__ __align__(16) float  g_w0q[320];      // 5x64 quantized
__device__ __align__(16) float  g_wq[3][4096];   // w1,w2,w3 quantized ([k][j])
__device__ __align__(16) float  g_w4q[64];       // 64x1 quantized
__device__ __align__(16) float  g_b0q[64];
__device__ __align__(16) float  g_bq[3][64];
__device__ __align__(16) float  g_b4q[4];        // only [0] used
__device__ float4 g_grid0[128];
__device__ float4 g_grid1[512];
__device__ float4 g_grid2[2048];

// ---------------- f32x2 packed helpers (Blackwell FFMA2 pipe) --------------
__device__ __forceinline__ unsigned long long pack2(float lo, float hi) {
    unsigned long long r;
    asm("mov.b64 %0, {%1, %2};" : "=l"(r) : "f"(lo), "f"(hi));
    return r;
}
__device__ __forceinline__ void unpack2(unsigned long long v, float& lo, float& hi) {
    asm("mov.b64 {%0, %1}, %2;" : "=f"(lo), "=f"(hi) : "l"(v));
}
__device__ __forceinline__ unsigned long long fma2(unsigned long long a,
                                                   unsigned long long b,
                                                   unsigned long long c) {
    unsigned long long d;
    asm("fma.rn.f32x2 %0, %1, %2, %3;" : "=l"(d) : "l"(a), "l"(b), "l"(c));
    return d;
}
__device__ __forceinline__ float rcp_fast(float x) {
    float r;
    asm("rcp.approx.f32 %0, %1;" : "=f"(r) : "f"(x));
    return r;
}

// ---------------- fast exact-enough GELU (A&S 7.1.26, |err_erf|<=1.5e-7) ----
__device__ __forceinline__ float gelu1(float x) {
    float z  = fabsf(x) * 0.70710678118654752f;
    float t  = rcp_fast(fmaf(0.3275911f, z, 1.0f));
    float q  = fmaf(1.061405429f, t, -1.453152027f);
    q = fmaf(q, t, 1.421413741f);
    q = fmaf(q, t, -0.284496736f);
    q = fmaf(q, t, 0.254829592f);
    float e  = __expf(-z * z);
    float s  = q * t;
    float ea = fmaf(-s, e, 1.0f);                      // erf(|x|/sqrt2)
    float er = __int_as_float(__float_as_int(ea) |
                              (__float_as_int(x) & 0x80000000)); // copysign
    float hx = 0.5f * x;
    return fmaf(hx, er, hx);
}

// ---------------- prep 1: weight quantization -------------------------------
// Q_LEVELS = 8**2 - 1 = 63 (per reference, NOT 2**8-1)
__global__ void quant_kernel(const float* w0, const float* w1, const float* w2,
                             const float* w3, const float* w4,
                             const float* b0, const float* b1, const float* b2,
                             const float* b3, const float* b4)
{
    __shared__ float smin[256], smax[256];
    const float* src; float* dst; int n;
    switch (blockIdx.x) {
        case 0: src = w0; dst = g_w0q;   n = 320;  break;
        case 1: src = w1; dst = g_wq[0]; n = 4096; break;
        case 2: src = w2; dst = g_wq[1]; n = 4096; break;
        case 3: src = w3; dst = g_wq[2]; n = 4096; break;
        case 4: src = w4; dst = g_w4q;   n = 64;   break;
        case 5: src = b0; dst = g_b0q;   n = 64;   break;
        case 6: src = b1; dst = g_bq[0]; n = 64;   break;
        case 7: src = b2; dst = g_bq[1]; n = 64;   break;
        case 8: src = b3; dst = g_bq[2]; n = 64;   break;
        default: src = b4; dst = g_b4q;  n = 1;    break;
    }
    int t = threadIdx.x;
    float mn = INFINITY, mx = -INFINITY;
    for (int i = t; i < n; i += 256) {
        float v = src[i];
        mn = fminf(mn, v); mx = fmaxf(mx, v);
    }
    smin[t] = mn; smax[t] = mx;
    __syncthreads();
    for (int s = 128; s > 0; s >>= 1) {
        if (t < s) {
            smin[t] = fminf(smin[t], smin[t + s]);
            smax[t] = fmaxf(smax[t], smax[t + s]);
        }
        __syncthreads();
    }
    mn = smin[0]; mx = smax[0];
    float scale = fmaxf(mx - mn, 1e-8f) / 63.0f;
    for (int i = t; i < n; i += 256) {
        // jnp.round is round-half-even -> rintf
        dst[i] = rintf((src[i] - mn) / scale) * scale + mn;
    }
}

// ---------------- prep 2: grid tables (STE forward == argmax gather) --------
__global__ void grid_kernel(const float* ind0, const float* cb0,
                            const float* ind1, const float* cb1,
                            const float* ind2, const float* cb2)
{
    int idx = blockIdx.x * blockDim.x + threadIdx.x;
    const float* ind; const float* cb; float4* dst; int row;
    if (idx < 128)       { ind = ind0; cb = cb0; dst = g_grid0; row = idx; }
    else if (idx < 640)  { ind = ind1; cb = cb1; dst = g_grid1; row = idx - 128; }
    else if (idx < 2688) { ind = ind2; cb = cb2; dst = g_grid2; row = idx - 640; }
    else return;
    const float* r = ind + (long)row * 64;
    float best = r[0]; int arg = 0;
    #pragma unroll
    for (int j = 1; j < 64; j++) {
        float v = r[j];
        if (v > best) { best = v; arg = j; }   // strict > == first-occurrence tie-break
    }
    dst[row] = make_float4(cb[arg * 4 + 0], cb[arg * 4 + 1],
                           cb[arg * 4 + 2], cb[arg * 4 + 3]);
}

// ---------------- main fused kernel -----------------------------------------
// Block = 256 threads = 256 points. Thread t: pgrp = t&63, jgrp = t>>6.
// Each thread computes outputs j in [16*jgrp, 16*jgrp+16) for the 4 points
// p_i = pgrp + 64*i. Activations live in k-major smem act[64][256]
// (conflict-free scalar LDS/STS); weights in smem, broadcast LDS.128.
#define WSZ 12288              // 3*4096 floats of weights
#define ASZ 16384              // 64*256 floats of activations
#define SMEM_BYTES ((WSZ + ASZ) * 4)

__global__ void __launch_bounds__(256, 2)
mlp_kernel(const float* __restrict__ x, float* __restrict__ out, int N)
{
    extern __shared__ float sm[];
    float* ws  = sm;          // [3][4096]
    float* act = sm + WSZ;    // [64][256]

    int t = threadIdx.x;

    // stage quantized 64x64 weights into smem (float4 copies)
    {
        const float4* src = (const float4*)g_wq;
        float4* dst = (float4*)ws;
        #pragma unroll
        for (int i = 0; i < 12; i++)
            dst[t + 256 * i] = src[t + 256 * i];
    }

    // ---- interp: one point per thread, write in5 to act rows 0..4 ----
    int gidx = blockIdx.x * 256 + t;
    {
        float2 xv = ((const float2*)x)[gidx];
        float feat = xv.x;
        float tc = (xv.y + 1.0f) * 0.5f;

        float4 g = make_float4(0.f, 0.f, 0.f, 0.f);
        auto interp_add = [&](const float4* __restrict__ tab, int res) {
            float c = tc * (float)(res - 1);
            int left  = min((int)floorf(c), res - 2);
            int right = max((int)ceilf(c), 1);
            float w = c - (float)left;
            float4 gl = __ldg(tab + left);
            float4 gr = __ldg(tab + right);
            g.x += (1.0f - w) * gl.x + w * gr.x;
            g.y += (1.0f - w) * gl.y + w * gr.y;
            g.z += (1.0f - w) * gl.z + w * gr.z;
            g.w += (1.0f - w) * gl.w + w * gr.w;
        };
        interp_add(g_grid0, 128);
        interp_add(g_grid1, 512);
        interp_add(g_grid2, 2048);

        __syncthreads();   // weight staging done before act writes reuse nothing; also orders smem
        act[0 * 256 + t] = g.x;
        act[1 * 256 + t] = g.y;
        act[2 * 256 + t] = g.z;
        act[3 * 256 + t] = g.w;
        act[4 * 256 + t] = feat;
    }
    __syncthreads();

    int pg = t & 63;
    int jg = t >> 6;
    int j0 = jg * 16;

    unsigned long long acc[4][8];

    // ---- layer 0: K=5 -> 64 ----
    {
        unsigned long long bias[8];
        const ulonglong2* bp = (const ulonglong2*)(g_b0q + j0);
        #pragma unroll
        for (int q = 0; q < 4; q++) {
            ulonglong2 b = __ldg(bp + q);
            bias[2 * q] = b.x; bias[2 * q + 1] = b.y;
        }
        #pragma unroll
        for (int i = 0; i < 4; i++)
            #pragma unroll
            for (int jj = 0; jj < 8; jj++)
                acc[i][jj] = bias[jj];

        #pragma unroll
        for (int k = 0; k < 5; k++) {
            unsigned long long w[8];
            const ulonglong2* wp = (const ulonglong2*)(g_w0q + k * 64 + j0);
            #pragma unroll
            for (int q = 0; q < 4; q++) {
                ulonglong2 wv = __ldg(wp + q);
                w[2 * q] = wv.x; w[2 * q + 1] = wv.y;
            }
            #pragma unroll
            for (int i = 0; i < 4; i++) {
                float a = act[k * 256 + pg + 64 * i];
                unsigned long long aa = pack2(a, a);
                #pragma unroll
                for (int jj = 0; jj < 8; jj++)
                    acc[i][jj] = fma2(aa, w[jj], acc[i][jj]);
            }
        }
    }

    // gelu + write (rows j0..j0+15)
    __syncthreads();
    #pragma unroll
    for (int i = 0; i < 4; i++) {
        #pragma unroll
        for (int jj = 0; jj < 8; jj++) {
            float lo, hi;
            unpack2(acc[i][jj], lo, hi);
            act[(j0 + 2 * jj)     * 256 + pg + 64 * i] = gelu1(lo);
            act[(j0 + 2 * jj + 1) * 256 + pg + 64 * i] = gelu1(hi);
        }
    }
    __syncthreads();

    // ---- layers 1..3: 64 -> 64 ----
    #pragma unroll 1
    for (int l = 0; l < 3; l++) {
        {
            const ulonglong2* bp = (const ulonglong2*)(g_bq[l] + j0);
            unsigned long long bias[8];
            #pragma unroll
            for (int q = 0; q < 4; q++) {
                ulonglong2 b = __ldg(bp + q);
                bias[2 * q] = b.x; bias[2 * q + 1] = b.y;
            }
            #pragma unroll
            for (int i = 0; i < 4; i++)
                #pragma unroll
                for (int jj = 0; jj < 8; jj++)
                    acc[i][jj] = bias[jj];
        }

        const float* wl = ws + l * 4096;
        #pragma unroll 8
        for (int k = 0; k < 64; k++) {
            unsigned long long w[8];
            const ulonglong2* wp = (const ulonglong2*)(wl + k * 64 + j0);
            #pragma unroll
            for (int q = 0; q < 4; q++) {
                ulonglong2 wv = wp[q];
                w[2 * q] = wv.x; w[2 * q + 1] = wv.y;
            }
            #pragma unroll
            for (int i = 0; i < 4; i++) {
                float a = act[k * 256 + pg + 64 * i];
                unsigned long long aa = pack2(a, a);
                #pragma unroll
                for (int jj = 0; jj < 8; jj++)
                    acc[i][jj] = fma2(aa, w[jj], acc[i][jj]);
            }
        }

        __syncthreads();
        #pragma unroll
        for (int i = 0; i < 4; i++) {
            #pragma unroll
            for (int jj = 0; jj < 8; jj++) {
                float lo, hi;
                unpack2(acc[i][jj], lo, hi);
                act[(j0 + 2 * jj)     * 256 + pg + 64 * i] = gelu1(lo);
                act[(j0 + 2 * jj + 1) * 256 + pg + 64 * i] = gelu1(hi);
            }
        }
        __syncthreads();
    }

    // ---- final: 64 -> 1, tanh (one point per thread) ----
    {
        unsigned long long v2 = pack2(__ldg(g_b4q), 0.0f);
        const unsigned long long* w4p = (const unsigned long long*)g_w4q;
        #pragma unroll
        for (int kk = 0; kk < 32; kk++) {
            float a0 = act[(2 * kk)     * 256 + t];
            float a1 = act[(2 * kk + 1) * 256 + t];
            v2 = fma2(pack2(a0, a1), __ldg(w4p + kk), v2);
        }
        float vlo, vhi;
        unpack2(v2, vlo, vhi);
        out[gidx] = tanhf(vlo + vhi);
    }
}

// ---------------- launch ----------------
extern "C" void kernel_launch(void* const* d_in, const int* in_sizes, int n_in,
                              void* d_out, int out_size)
{
    const float* x    = (const float*)d_in[0];
    const float* cb0  = (const float*)d_in[1];
    const float* ind0 = (const float*)d_in[2];
    const float* cb1  = (const float*)d_in[3];
    const float* ind1 = (const float*)d_in[4];
    const float* cb2  = (const float*)d_in[5];
    const float* ind2 = (const float*)d_in[6];
    const float* w0   = (const float*)d_in[7];
    const float* b0   = (const float*)d_in[8];
    const float* w1   = (const float*)d_in[9];
    const float* b1   = (const float*)d_in[10];
    const float* w2   = (const float*)d_in[11];
    const float* b2   = (const float*)d_in[12];
    const float* w3   = (const float*)d_in[13];
    const float* b3   = (const float*)d_in[14];
    const float* w4   = (const float*)d_in[15];
    const float* b4   = (const float*)d_in[16];

    int N = in_sizes[0] / 2;

    cudaFuncSetAttribute(mlp_kernel,
                         cudaFuncAttributeMaxDynamicSharedMemorySize, SMEM_BYTES);

    quant_kernel<<<10, 256>>>(w0, w1, w2, w3, w4, b0, b1, b2, b3, b4);
    grid_kernel<<<(2688 + 255) / 256, 256>>>(ind0, cb0, ind1, cb1, ind2, cb2);
    mlp_kernel<<<N / 256, 256, SMEM_BYTES>>>(x, (float*)d_out, N);
}

// round 5
// speedup vs baseline: 2.1459x; 1.1470x over previous
#include <cuda_runtime.h>
#include <math.h>
#include <stdint.h>

typedef unsigned long long u64;

// ---------------- device-global scratch (no allocs allowed) ----------------
__device__ __align__(16) float  g_w0q[320];      // 5x64 quantized
__device__ __align__(16) float  g_wq[3][4096];   // w1,w2,w3 quantized ([k][j])
__device__ __align__(16) float  g_w4q[64];
__device__ __align__(16) float  g_b0q[64];
__device__ __align__(16) float  g_bq[3][64];
__device__ __align__(16) float  g_b4q[4];
__device__ float4 g_grid0[128];
__device__ float4 g_grid1[512];
__device__ float4 g_grid2[2048];

// ---------------- f32x2 packed helpers --------------------------------------
__device__ __forceinline__ u64 pack2(float lo, float hi) {
    u64 r;
    asm("mov.b64 %0, {%1, %2};" : "=l"(r) : "f"(lo), "f"(hi));
    return r;
}
__device__ __forceinline__ void unpack2(u64 v, float& lo, float& hi) {
    asm("mov.b64 {%0, %1}, %2;" : "=f"(lo), "=f"(hi) : "l"(v));
}
__device__ __forceinline__ u64 fma2(u64 a, u64 b, u64 c) {
    u64 d;
    asm("fma.rn.f32x2 %0, %1, %2, %3;" : "=l"(d) : "l"(a), "l"(b), "l"(c));
    return d;
}
__device__ __forceinline__ u64 mul2(u64 a, u64 b) {
    u64 d;
    asm("mul.rn.f32x2 %0, %1, %2;" : "=l"(d) : "l"(a), "l"(b));
    return d;
}
__device__ __forceinline__ u64 dup2(float c) { return pack2(c, c); }

__device__ __forceinline__ float rcp_fast(float x) {
    float r;
    asm("rcp.approx.f32 %0, %1;" : "=f"(r) : "f"(x));
    return r;
}
__device__ __forceinline__ float ex2_fast(float x) {
    float r;
    asm("ex2.approx.f32 %0, %1;" : "=f"(r) : "f"(x));
    return r;
}
__device__ __forceinline__ u64 rcp2(u64 a) {
    float l, h;
    unpack2(a, l, h);
    return pack2(rcp_fast(l), rcp_fast(h));
}
__device__ __forceinline__ u64 ex22(u64 a) {
    float l, h;
    unpack2(a, l, h);
    return pack2(ex2_fast(l), ex2_fast(h));
}

// ---------------- packed GELU (A&S 7.1.26, |erf err| <= 1.5e-7) -------------
__device__ __forceinline__ u64 gelu2p(u64 v) {
    const u64 ABS2 = 0x7fffffff7fffffffULL;
    const u64 SGN2 = 0x8000000080000000ULL;
    u64 ONE2 = dup2(1.0f);
    u64 ax = v & ABS2;
    u64 z  = mul2(ax, dup2(0.70710678118654752f));
    u64 t  = rcp2(fma2(z, dup2(0.3275911f), ONE2));
    // negated-coefficient poly: q = -P(t)
    u64 q  = fma2(dup2(-1.061405429f), t, dup2(1.453152027f));
    q = fma2(q, t, dup2(-1.421413741f));
    q = fma2(q, t, dup2(0.284496736f));
    q = fma2(q, t, dup2(-0.254829592f));
    u64 s  = mul2(q, t);                       // = -P(t)*t
    u64 z2 = mul2(z, z);
    u64 e  = ex22(mul2(z2, dup2(-1.4426950408889634f)));  // e^{-z^2}
    u64 ea = fma2(s, e, ONE2);                 // erf(|x|/sqrt2) in (0,1)
    u64 er = ea | (v & SGN2);                  // copysign
    u64 hx = mul2(v, dup2(0.5f));
    return fma2(hx, er, hx);
}

// ---------------- prep 1: weight quantization (Q_LEVELS = 63) --------------
__global__ void quant_kernel(const float* w0, const float* w1, const float* w2,
                             const float* w3, const float* w4,
                             const float* b0, const float* b1, const float* b2,
                             const float* b3, const float* b4)
{
    __shared__ float smin[256], smax[256];
    const float* src; float* dst; int n;
    switch (blockIdx.x) {
        case 0: src = w0; dst = g_w0q;   n = 320;  break;
        case 1: src = w1; dst = g_wq[0]; n = 4096; break;
        case 2: src = w2; dst = g_wq[1]; n = 4096; break;
        case 3: src = w3; dst = g_wq[2]; n = 4096; break;
        case 4: src = w4; dst = g_w4q;   n = 64;   break;
        case 5: src = b0; dst = g_b0q;   n = 64;   break;
        case 6: src = b1; dst = g_bq[0]; n = 64;   break;
        case 7: src = b2; dst = g_bq[1]; n = 64;   break;
        case 8: src = b3; dst = g_bq[2]; n = 64;   break;
        default: src = b4; dst = g_b4q;  n = 1;    break;
    }
    int t = threadIdx.x;
    float mn = INFINITY, mx = -INFINITY;
    for (int i = t; i < n; i += 256) {
        float v = src[i];
        mn = fminf(mn, v); mx = fmaxf(mx, v);
    }
    smin[t] = mn; smax[t] = mx;
    __syncthreads();
    for (int s = 128; s > 0; s >>= 1) {
        if (t < s) {
            smin[t] = fminf(smin[t], smin[t + s]);
            smax[t] = fmaxf(smax[t], smax[t + s]);
        }
        __syncthreads();
    }
    mn = smin[0]; mx = smax[0];
    float scale = fmaxf(mx - mn, 1e-8f) / 63.0f;
    for (int i = t; i < n; i += 256)
        dst[i] = rintf((src[i] - mn) / scale) * scale + mn;
}

// ---------------- prep 2: grid tables (STE forward == argmax gather) --------
__global__ void grid_kernel(const float* ind0, const float* cb0,
                            const float* ind1, const float* cb1,
                            const float* ind2, const float* cb2)
{
    int idx = blockIdx.x * blockDim.x + threadIdx.x;
    const float* ind; const float* cb; float4* dst; int row;
    if (idx < 128)       { ind = ind0; cb = cb0; dst = g_grid0; row = idx; }
    else if (idx < 640)  { ind = ind1; cb = cb1; dst = g_grid1; row = idx - 128; }
    else if (idx < 2688) { ind = ind2; cb = cb2; dst = g_grid2; row = idx - 640; }
    else return;
    const float* r = ind + (long)row * 64;
    float best = r[0]; int arg = 0;
    #pragma unroll
    for (int j = 1; j < 64; j++) {
        float v = r[j];
        if (v > best) { best = v; arg = j; }
    }
    dst[row] = make_float4(cb[arg * 4 + 0], cb[arg * 4 + 1],
                           cb[arg * 4 + 2], cb[arg * 4 + 3]);
}

// ---------------- main fused kernel -----------------------------------------
// 256 threads = 256 points/block. Thread t: pg = t&63, jg = t>>6.
// Computes outputs [16*jg, 16*jg+16) for points p_i = pg + 64i (i=0..3).
// Act smem layout: act[k][col] with col(p) = (p&63)*4 + (p>>6), so each
// thread's 4 points are 16B-contiguous -> LDS.128 / STS.128 everywhere.
#define WSZ 12288              // 3*4096 floats of weights
#define ASZ 16384              // 64*256 floats of activations
#define SMEM_BYTES ((WSZ + ASZ) * 4)

__global__ void __launch_bounds__(256, 2)
mlp_kernel(const float* __restrict__ x, float* __restrict__ out, int N)
{
    extern __shared__ float sm[];
    float* ws  = sm;          // [3][4096]
    float* act = sm + WSZ;    // [64][256] (permuted cols)

    int t = threadIdx.x;

    // stage quantized 64x64 weights into smem
    {
        const float4* src = (const float4*)g_wq;
        float4* dst = (float4*)ws;
        #pragma unroll
        for (int i = 0; i < 12; i++)
            dst[t + 256 * i] = src[t + 256 * i];
    }

    // ---- interp: one point per thread -> act rows 0..4 (permuted col) ----
    int gidx = blockIdx.x * 256 + t;
    {
        float2 xv = __ldg((const float2*)x + gidx);
        float feat = xv.x;
        float tc = (xv.y + 1.0f) * 0.5f;
        float4 g = make_float4(0.f, 0.f, 0.f, 0.f);
        auto interp_add = [&](const float4* __restrict__ tab, int res) {
            float c = tc * (float)(res - 1);
            int left  = min((int)floorf(c), res - 2);
            int right = max((int)ceilf(c), 1);
            float w = c - (float)left;
            float4 gl = __ldg(tab + left);
            float4 gr = __ldg(tab + right);
            g.x += (1.0f - w) * gl.x + w * gr.x;
            g.y += (1.0f - w) * gl.y + w * gr.y;
            g.z += (1.0f - w) * gl.z + w * gr.z;
            g.w += (1.0f - w) * gl.w + w * gr.w;
        };
        interp_add(g_grid0, 128);
        interp_add(g_grid1, 512);
        interp_add(g_grid2, 2048);

        int col = (t & 63) * 4 + (t >> 6);
        act[0 * 256 + col] = g.x;
        act[1 * 256 + col] = g.y;
        act[2 * 256 + col] = g.z;
        act[3 * 256 + col] = g.w;
        act[4 * 256 + col] = feat;
    }
    __syncthreads();

    int pg = t & 63;
    int jg = t >> 6;
    int j0 = jg * 16;

    u64 acc[4][8];   // [point i][j-pair jj] -> (j0+2jj, j0+2jj+1)

    // ---- layer 0: K=5 -> 64 ----
    {
        const u64* bp = (const u64*)g_b0q + jg * 8;
        u64 bias[8];
        #pragma unroll
        for (int jj = 0; jj < 8; jj++) bias[jj] = __ldg(bp + jj);
        #pragma unroll
        for (int i = 0; i < 4; i++)
            #pragma unroll
            for (int jj = 0; jj < 8; jj++) acc[i][jj] = bias[jj];

        #pragma unroll
        for (int k = 0; k < 5; k++) {
            u64 w[8];
            const ulonglong2* wp = (const ulonglong2*)(g_w0q + k * 64 + j0);
            #pragma unroll
            for (int q = 0; q < 4; q++) {
                ulonglong2 wv = __ldg(wp + q);
                w[2 * q] = wv.x; w[2 * q + 1] = wv.y;
            }
            float4 av = *(const float4*)(act + k * 256 + pg * 4);
            u64 aa[4] = { pack2(av.x, av.x), pack2(av.y, av.y),
                          pack2(av.z, av.z), pack2(av.w, av.w) };
            #pragma unroll
            for (int i = 0; i < 4; i++)
                #pragma unroll
                for (int jj = 0; jj < 8; jj++)
                    acc[i][jj] = fma2(aa[i], w[jj], acc[i][jj]);
        }
    }

    // gelu + vectorized write
    __syncthreads();
    #pragma unroll
    for (int jj = 0; jj < 8; jj++) {
        float lo[4], hi[4];
        #pragma unroll
        for (int i = 0; i < 4; i++) {
            u64 g = gelu2p(acc[i][jj]);
            unpack2(g, lo[i], hi[i]);
        }
        *(float4*)(act + (j0 + 2 * jj) * 256 + pg * 4) =
            make_float4(lo[0], lo[1], lo[2], lo[3]);
        *(float4*)(act + (j0 + 2 * jj + 1) * 256 + pg * 4) =
            make_float4(hi[0], hi[1], hi[2], hi[3]);
    }
    __syncthreads();

    // ---- layers 1..3: 64 -> 64 ----
    #pragma unroll 1
    for (int l = 0; l < 3; l++) {
        {
            const u64* bp = (const u64*)g_bq[l] + jg * 8;
            u64 bias[8];
            #pragma unroll
            for (int jj = 0; jj < 8; jj++) bias[jj] = __ldg(bp + jj);
            #pragma unroll
            for (int i = 0; i < 4; i++)
                #pragma unroll
                for (int jj = 0; jj < 8; jj++) acc[i][jj] = bias[jj];
        }

        const float* wl = ws + l * 4096;
        #pragma unroll 8
        for (int k = 0; k < 64; k++) {
            u64 w[8];
            const ulonglong2* wp = (const ulonglong2*)(wl + k * 64 + j0);
            #pragma unroll
            for (int q = 0; q < 4; q++) {
                ulonglong2 wv = wp[q];
                w[2 * q] = wv.x; w[2 * q + 1] = wv.y;
            }
            float4 av = *(const float4*)(act + k * 256 + pg * 4);
            u64 aa[4] = { pack2(av.x, av.x), pack2(av.y, av.y),
                          pack2(av.z, av.z), pack2(av.w, av.w) };
            #pragma unroll
            for (int i = 0; i < 4; i++)
                #pragma unroll
                for (int jj = 0; jj < 8; jj++)
                    acc[i][jj] = fma2(aa[i], w[jj], acc[i][jj]);
        }

        if (l < 2) {
            __syncthreads();
            #pragma unroll
            for (int jj = 0; jj < 8; jj++) {
                float lo[4], hi[4];
                #pragma unroll
                for (int i = 0; i < 4; i++) {
                    u64 g = gelu2p(acc[i][jj]);
                    unpack2(g, lo[i], hi[i]);
                }
                *(float4*)(act + (j0 + 2 * jj) * 256 + pg * 4) =
                    make_float4(lo[0], lo[1], lo[2], lo[3]);
                *(float4*)(act + (j0 + 2 * jj + 1) * 256 + pg * 4) =
                    make_float4(hi[0], hi[1], hi[2], hi[3]);
            }
            __syncthreads();
        } else {
            // fused final layer: partial dot per j-group, reduce via smem
            u64 dot[4];
            const u64* w4p = (const u64*)g_w4q + jg * 8;
            #pragma unroll
            for (int i = 0; i < 4; i++) dot[i] = pack2(0.0f, 0.0f);
            #pragma unroll
            for (int jj = 0; jj < 8; jj++) {
                u64 wv = __ldg(w4p + jj);
                #pragma unroll
                for (int i = 0; i < 4; i++)
                    dot[i] = fma2(gelu2p(acc[i][jj]), wv, dot[i]);
            }
            __syncthreads();   // all act reads done; reuse rows 0..3 as psum
            #pragma unroll
            for (int i = 0; i < 4; i++) {
                float dl, dh;
                unpack2(dot[i], dl, dh);
                act[jg * 256 + (pg + 64 * i)] = dl + dh;
            }
            __syncthreads();
            float s = act[t] + act[256 + t] + act[512 + t] + act[768 + t]
                    + __ldg(g_b4q);
            out[gidx] = tanhf(s);
        }
    }
}

// ---------------- launch ----------------
extern "C" void kernel_launch(void* const* d_in, const int* in_sizes, int n_in,
                              void* d_out, int out_size)
{
    const float* x    = (const float*)d_in[0];
    const float* cb0  = (const float*)d_in[1];
    const float* ind0 = (const float*)d_in[2];
    const float* cb1  = (const float*)d_in[3];
    const float* ind1 = (const float*)d_in[4];
    const float* cb2  = (const float*)d_in[5];
    const float* ind2 = (const float*)d_in[6];
    const float* w0   = (const float*)d_in[7];
    const float* b0   = (const float*)d_in[8];
    const float* w1   = (const float*)d_in[9];
    const float* b1   = (const float*)d_in[10];
    const float* w2   = (const float*)d_in[11];
    const float* b2   = (const float*)d_in[12];
    const float* w3   = (const float*)d_in[13];
    const float* b3   = (const float*)d_in[14];
    const float* w4   = (const float*)d_in[15];
    const float* b4   = (const float*)d_in[16];

    int N = in_sizes[0] / 2;

    cudaFuncSetAttribute(mlp_kernel,
                         cudaFuncAttributeMaxDynamicSharedMemorySize, SMEM_BYTES);

    quant_kernel<<<10, 256>>>(w0, w1, w2, w3, w4, b0, b1, b2, b3, b4);
    grid_kernel<<<(2688 + 255) / 256, 256>>>(ind0, cb0, ind1, cb1, ind2, cb2);
    mlp_kernel<<<N / 256, 256, SMEM_BYTES>>>(x, (float*)d_out, N);
}

// round 6
// speedup vs baseline: 3.4197x; 1.5936x over previous
#include <cuda_runtime.h>
#include <math.h>
#include <stdint.h>

typedef unsigned long long u64;

// ---------------- device-global scratch (no allocs allowed) ----------------
__device__ __align__(16) float  g_w0q[320];      // 5x64 quantized
__device__ __align__(16) float  g_wq[3][4096];   // w1,w2,w3 quantized ([k][j])
__device__ __align__(16) float  g_w4q[64];
__device__ __align__(16) float  g_b0q[64];
__device__ __align__(16) float  g_bq[3][64];
__device__ __align__(16) float  g_b4q[4];
__device__ float4 g_grid0[128];
__device__ float4 g_grid1[512];
__device__ float4 g_grid2[2048];

// ---------------- packed helpers -------------------------------------------
__device__ __forceinline__ u64 pack2(float lo, float hi) {
    u64 r;
    asm("mov.b64 %0, {%1, %2};" : "=l"(r) : "f"(lo), "f"(hi));
    return r;
}
__device__ __forceinline__ void unpack2(u64 v, float& lo, float& hi) {
    asm("mov.b64 {%0, %1}, %2;" : "=f"(lo), "=f"(hi) : "l"(v));
}
__device__ __forceinline__ u64 fma2(u64 a, u64 b, u64 c) {
    u64 d;
    asm("fma.rn.f32x2 %0, %1, %2, %3;" : "=l"(d) : "l"(a), "l"(b), "l"(c));
    return d;
}
__device__ __forceinline__ u64 mul2(u64 a, u64 b) {
    u64 d;
    asm("mul.rn.f32x2 %0, %1, %2;" : "=l"(d) : "l"(a), "l"(b));
    return d;
}
__device__ __forceinline__ u64 dup2(float c) { return pack2(c, c); }
__device__ __forceinline__ float rcp_fast(float x) {
    float r; asm("rcp.approx.f32 %0, %1;" : "=f"(r) : "f"(x)); return r;
}
__device__ __forceinline__ float ex2_fast(float x) {
    float r; asm("ex2.approx.f32 %0, %1;" : "=f"(r) : "f"(x)); return r;
}
__device__ __forceinline__ u64 rcp2(u64 a) {
    float l, h; unpack2(a, l, h); return pack2(rcp_fast(l), rcp_fast(h));
}
__device__ __forceinline__ u64 ex22(u64 a) {
    float l, h; unpack2(a, l, h); return pack2(ex2_fast(l), ex2_fast(h));
}
__device__ __forceinline__ uint32_t bf16x2_rn(float hi, float lo) {
    uint32_t r;
    asm("cvt.rn.bf16x2.f32 %0, %1, %2;" : "=r"(r) : "f"(hi), "f"(lo));
    return r;   // lo16 = bf16(lo), hi16 = bf16(hi)
}

// packed GELU (A&S 7.1.26, |erf err| <= 1.5e-7)
__device__ __forceinline__ u64 gelu2p(u64 v) {
    const u64 ABS2 = 0x7fffffff7fffffffULL;
    const u64 SGN2 = 0x8000000080000000ULL;
    u64 ONE2 = dup2(1.0f);
    u64 ax = v & ABS2;
    u64 z  = mul2(ax, dup2(0.70710678118654752f));
    u64 t  = rcp2(fma2(z, dup2(0.3275911f), ONE2));
    u64 q  = fma2(dup2(-1.061405429f), t, dup2(1.453152027f));
    q = fma2(q, t, dup2(-1.421413741f));
    q = fma2(q, t, dup2(0.284496736f));
    q = fma2(q, t, dup2(-0.254829592f));
    u64 s  = mul2(q, t);
    u64 z2 = mul2(z, z);
    u64 e  = ex22(mul2(z2, dup2(-1.4426950408889634f)));
    u64 ea = fma2(s, e, ONE2);
    u64 er = ea | (v & SGN2);
    u64 hx = mul2(v, dup2(0.5f));
    return fma2(hx, er, hx);
}

// bf16 tensor-core mma (base PTX, sm_80+): D += A x B
__device__ __forceinline__ void mma_bf16(float d[4], const uint32_t a[4],
                                         uint32_t b0, uint32_t b1) {
    asm volatile(
        "mma.sync.aligned.m16n8k16.row.col.f32.bf16.bf16.f32 "
        "{%0,%1,%2,%3}, {%4,%5,%6,%7}, {%8,%9}, {%0,%1,%2,%3};"
        : "+f"(d[0]), "+f"(d[1]), "+f"(d[2]), "+f"(d[3])
        : "r"(a[0]), "r"(a[1]), "r"(a[2]), "r"(a[3]), "r"(b0), "r"(b1));
}

// ---------------- prep 1: weight quantization (Q_LEVELS = 63) --------------
__global__ void quant_kernel(const float* w0, const float* w1, const float* w2,
                             const float* w3, const float* w4,
                             const float* b0, const float* b1, const float* b2,
                             const float* b3, const float* b4)
{
    __shared__ float smin[256], smax[256];
    const float* src; float* dst; int n;
    switch (blockIdx.x) {
        case 0: src = w0; dst = g_w0q;   n = 320;  break;
        case 1: src = w1; dst = g_wq[0]; n = 4096; break;
        case 2: src = w2; dst = g_wq[1]; n = 4096; break;
        case 3: src = w3; dst = g_wq[2]; n = 4096; break;
        case 4: src = w4; dst = g_w4q;   n = 64;   break;
        case 5: src = b0; dst = g_b0q;   n = 64;   break;
        case 6: src = b1; dst = g_bq[0]; n = 64;   break;
        case 7: src = b2; dst = g_bq[1]; n = 64;   break;
        case 8: src = b3; dst = g_bq[2]; n = 64;   break;
        default: src = b4; dst = g_b4q;  n = 1;    break;
    }
    int t = threadIdx.x;
    float mn = INFINITY, mx = -INFINITY;
    for (int i = t; i < n; i += 256) {
        float v = src[i];
        mn = fminf(mn, v); mx = fmaxf(mx, v);
    }
    smin[t] = mn; smax[t] = mx;
    __syncthreads();
    for (int s = 128; s > 0; s >>= 1) {
        if (t < s) {
            smin[t] = fminf(smin[t], smin[t + s]);
            smax[t] = fmaxf(smax[t], smax[t + s]);
        }
        __syncthreads();
    }
    mn = smin[0]; mx = smax[0];
    float scale = fmaxf(mx - mn, 1e-8f) / 63.0f;
    for (int i = t; i < n; i += 256)
        dst[i] = rintf((src[i] - mn) / scale) * scale + mn;
}

// ---------------- prep 2: grid tables (STE forward == argmax gather) --------
__global__ void grid_kernel(const float* ind0, const float* cb0,
                            const float* ind1, const float* cb1,
                            const float* ind2, const float* cb2)
{
    int idx = blockIdx.x * blockDim.x + threadIdx.x;
    const float* ind; const float* cb; float4* dst; int row;
    if (idx < 128)       { ind = ind0; cb = cb0; dst = g_grid0; row = idx; }
    else if (idx < 640)  { ind = ind1; cb = cb1; dst = g_grid1; row = idx - 128; }
    else if (idx < 2688) { ind = ind2; cb = cb2; dst = g_grid2; row = idx - 640; }
    else return;
    const float* r = ind + (long)row * 64;
    float best = r[0]; int arg = 0;
    #pragma unroll
    for (int j = 1; j < 64; j++) {
        float v = r[j];
        if (v > best) { best = v; arg = j; }
    }
    dst[row] = make_float4(cb[arg * 4 + 0], cb[arg * 4 + 1],
                           cb[arg * 4 + 2], cb[arg * 4 + 3]);
}

// ---------------- main tensor-core kernel -----------------------------------
// Block = 128 threads (4 warps), persistent grid-stride over 128-pt tiles.
// Each warp handles 2 sequential m16 sub-tiles (16 pts each), fully
// register-resident: the m16n8 D layout == m16k16 A layout, so bias+gelu+
// bf16 hi/lo split map D->A without any cross-thread traffic.
//
// smem (bytes):
//   0     : wf  — B fragments [3l][4kt][8nt][32 lanes] x uint4{b0hi,b1hi,b0lo,b1lo} = 49152
//   49152 : w0s [320f]
//   50432 : b0s [64f]
//   50688 : bz  [3][64f]
//   51456 : w4s [64f]
//   51712 : b4f [4f]
//   51728 : in5s [5][128f]
#define OFF_WF    0
#define OFF_W0S   49152
#define OFF_B0S   50432
#define OFF_BZ    50688
#define OFF_W4S   51456
#define OFF_B4F   51712
#define OFF_IN5   51728
#define SMEM_BYTES 54288

__global__ void __launch_bounds__(128, 4)
mlp_tc_kernel(const float* __restrict__ x, float* __restrict__ out, int ntiles)
{
    extern __shared__ char smp[];
    const uint4* wf  = (const uint4*)(smp + OFF_WF);
    float* w0s = (float*)(smp + OFF_W0S);
    float* b0s = (float*)(smp + OFF_B0S);
    float* bz  = (float*)(smp + OFF_BZ);
    float* w4s = (float*)(smp + OFF_W4S);
    float* b4f = (float*)(smp + OFF_B4F);
    float* in5s = (float*)(smp + OFF_IN5);

    int t = threadIdx.x;
    int wid = t >> 5;
    int lane = t & 31;
    int g = lane >> 2;      // row group 0..7
    int tig = lane & 3;     // thread-in-group

    // ---- one-time staging ----
    // B fragments with bf16 hi/lo split
    {
        uint4* wfw = (uint4*)(smp + OFF_WF);
        for (int e = t; e < 3072; e += 128) {
            int el = e & 31, nt = (e >> 5) & 7, kt = (e >> 8) & 3, l = e >> 10;
            int eg = el >> 2, etig = el & 3;
            int j = 8 * nt + eg;
            int k0 = 16 * kt + 2 * etig;
            const float* wl = g_wq[l];
            float w0v = wl[(k0    ) * 64 + j];
            float w1v = wl[(k0 + 1) * 64 + j];
            float w8v = wl[(k0 + 8) * 64 + j];
            float w9v = wl[(k0 + 9) * 64 + j];
            uint32_t h01 = bf16x2_rn(w1v, w0v);
            uint32_t h89 = bf16x2_rn(w9v, w8v);
            float r0 = __uint_as_float(h01 << 16);
            float r1 = __uint_as_float(h01 & 0xffff0000u);
            float r8 = __uint_as_float(h89 << 16);
            float r9 = __uint_as_float(h89 & 0xffff0000u);
            uint32_t l01 = bf16x2_rn(w1v - r1, w0v - r0);
            uint32_t l89 = bf16x2_rn(w9v - r9, w8v - r8);
            wfw[e] = make_uint4(h01, h89, l01, l89);
        }
    }
    for (int i = t; i < 320; i += 128) w0s[i] = g_w0q[i];
    if (t < 64) {
        b0s[t] = g_b0q[t];
        bz[t] = g_bq[0][t]; bz[64 + t] = g_bq[1][t]; bz[128 + t] = g_bq[2][t];
        w4s[t] = g_w4q[t];
        if (t == 0) b4f[0] = g_b4q[0];
    }

    for (int tile = blockIdx.x; tile < ntiles; tile += gridDim.x) {
        __syncthreads();   // in5s safe to overwrite / staging visible

        // ---- interp: one point per thread -> in5s[5][128] ----
        int gidx = tile * 128 + t;
        {
            float2 xv = __ldg((const float2*)x + gidx);
            float feat = xv.x;
            float tc = (xv.y + 1.0f) * 0.5f;
            float4 gg = make_float4(0.f, 0.f, 0.f, 0.f);
            auto interp_add = [&](const float4* __restrict__ tab, int res) {
                float c = tc * (float)(res - 1);
                int left  = min((int)floorf(c), res - 2);
                int right = max((int)ceilf(c), 1);
                float w = c - (float)left;
                float4 gl = __ldg(tab + left);
                float4 gr = __ldg(tab + right);
                gg.x += (1.0f - w) * gl.x + w * gr.x;
                gg.y += (1.0f - w) * gl.y + w * gr.y;
                gg.z += (1.0f - w) * gl.z + w * gr.z;
                gg.w += (1.0f - w) * gl.w + w * gr.w;
            };
            interp_add(g_grid0, 128);
            interp_add(g_grid1, 512);
            interp_add(g_grid2, 2048);
            in5s[0 * 128 + t] = gg.x;
            in5s[1 * 128 + t] = gg.y;
            in5s[2 * 128 + t] = gg.z;
            in5s[3 * 128 + t] = gg.w;
            in5s[4 * 128 + t] = feat;
        }
        __syncthreads();

        // ---- each warp: 2 sequential m16 sub-tiles ----
        #pragma unroll 1
        for (int s = 0; s < 2; s++) {
            int mt = wid + 4 * s;          // m-tile 0..7
            int poff = mt * 16;            // point offset in tile

            float d[8][4];
            uint32_t Ahi[4][4], Alo[4][4];

            // ---- layer 0 (5 -> 64) into D layout ----
            {
                float ia[5], ib[5];
                #pragma unroll
                for (int k = 0; k < 5; k++) {
                    ia[k] = in5s[k * 128 + poff + g];
                    ib[k] = in5s[k * 128 + poff + g + 8];
                }
                #pragma unroll
                for (int nt = 0; nt < 8; nt++) {
                    int f0 = 8 * nt + 2 * tig;
                    u64 a0 = pack2(0.f, 0.f), a1 = pack2(0.f, 0.f);
                    #pragma unroll
                    for (int k = 0; k < 5; k++) {
                        u64 wp = *(const u64*)(w0s + k * 64 + f0);
                        a0 = fma2(dup2(ia[k]), wp, a0);
                        a1 = fma2(dup2(ib[k]), wp, a1);
                    }
                    unpack2(a0, d[nt][0], d[nt][1]);
                    unpack2(a1, d[nt][2], d[nt][3]);
                }
            }

            // ---- epilogue D -> A (bias, gelu, bf16 hi/lo split) ----
            auto epi = [&](const float* bias) {
                #pragma unroll
                for (int nt = 0; nt < 8; nt++) {
                    int f0 = 8 * nt + 2 * tig;
                    float2 bb = *(const float2*)(bias + f0);
                    u64 p01 = gelu2p(pack2(d[nt][0] + bb.x, d[nt][1] + bb.y));
                    u64 p23 = gelu2p(pack2(d[nt][2] + bb.x, d[nt][3] + bb.y));
                    float g0, g1, g2, g3;
                    unpack2(p01, g0, g1);
                    unpack2(p23, g2, g3);
                    uint32_t h01 = bf16x2_rn(g1, g0);
                    uint32_t h23 = bf16x2_rn(g3, g2);
                    float r0 = __uint_as_float(h01 << 16);
                    float r1 = __uint_as_float(h01 & 0xffff0000u);
                    float r2 = __uint_as_float(h23 << 16);
                    float r3 = __uint_as_float(h23 & 0xffff0000u);
                    uint32_t q01 = bf16x2_rn(g1 - r1, g0 - r0);
                    uint32_t q23 = bf16x2_rn(g3 - r3, g2 - r2);
                    int kt = nt >> 1;
                    int o = (nt & 1) ? 2 : 0;
                    Ahi[kt][o] = h01; Ahi[kt][o + 1] = h23;
                    Alo[kt][o] = q01; Alo[kt][o + 1] = q23;
                }
            };
            epi(b0s);

            // ---- 3 mma layers ----
            #pragma unroll 1
            for (int l = 0; l < 3; l++) {
                #pragma unroll
                for (int nt = 0; nt < 8; nt++) {
                    d[nt][0] = 0.f; d[nt][1] = 0.f;
                    d[nt][2] = 0.f; d[nt][3] = 0.f;
                }
                const uint4* wfl = wf + (size_t)l * 4 * 8 * 32;
                #pragma unroll
                for (int kt = 0; kt < 4; kt++) {
                    #pragma unroll
                    for (int nt = 0; nt < 8; nt++) {
                        uint4 B = wfl[(kt * 8 + nt) * 32 + lane];
                        mma_bf16(d[nt], Ahi[kt], B.x, B.y);   // hi*hi
                        mma_bf16(d[nt], Ahi[kt], B.z, B.w);   // hi*lo
                        mma_bf16(d[nt], Alo[kt], B.x, B.y);   // lo*hi
                    }
                }
                if (l < 2) epi(bz + 64 * l);
            }

            // ---- final: bias b3, gelu, dot w4, reduce, tanh ----
            {
                const float* b3 = bz + 128;
                u64 dg = pack2(0.f, 0.f), dg8 = pack2(0.f, 0.f);
                #pragma unroll
                for (int nt = 0; nt < 8; nt++) {
                    int f0 = 8 * nt + 2 * tig;
                    float2 bb = *(const float2*)(b3 + f0);
                    u64 p01 = gelu2p(pack2(d[nt][0] + bb.x, d[nt][1] + bb.y));
                    u64 p23 = gelu2p(pack2(d[nt][2] + bb.x, d[nt][3] + bb.y));
                    u64 w4p = *(const u64*)(w4s + f0);
                    dg  = fma2(p01, w4p, dg);
                    dg8 = fma2(p23, w4p, dg8);
                }
                float a, b, sg, sg8;
                unpack2(dg, a, b);  sg  = a + b;
                unpack2(dg8, a, b); sg8 = a + b;
                sg  += __shfl_xor_sync(0xffffffffu, sg, 1);
                sg  += __shfl_xor_sync(0xffffffffu, sg, 2);
                sg8 += __shfl_xor_sync(0xffffffffu, sg8, 1);
                sg8 += __shfl_xor_sync(0xffffffffu, sg8, 2);
                if (tig == 0) {
                    float bb4 = b4f[0];
                    int base = tile * 128 + poff;
                    out[base + g]     = tanhf(sg + bb4);
                    out[base + g + 8] = tanhf(sg8 + bb4);
                }
            }
        }
    }
}

// ---------------- launch ----------------
extern "C" void kernel_launch(void* const* d_in, const int* in_sizes, int n_in,
                              void* d_out, int out_size)
{
    const float* x    = (const float*)d_in[0];
    const float* cb0  = (const float*)d_in[1];
    const float* ind0 = (const float*)d_in[2];
    const float* cb1  = (const float*)d_in[3];
    const float* ind1 = (const float*)d_in[4];
    const float* cb2  = (const float*)d_in[5];
    const float* ind2 = (const float*)d_in[6];
    const float* w0   = (const float*)d_in[7];
    const float* b0   = (const float*)d_in[8];
    const float* w1   = (const float*)d_in[9];
    const float* b1   = (const float*)d_in[10];
    const float* w2   = (const float*)d_in[11];
    const float* b2   = (const float*)d_in[12];
    const float* w3   = (const float*)d_in[13];
    const float* b3   = (const float*)d_in[14];
    const float* w4   = (const float*)d_in[15];
    const float* b4   = (const float*)d_in[16];

    int N = in_sizes[0] / 2;
    int ntiles = N / 128;

    static int configured = 0;
    if (!configured) {
        cudaFuncSetAttribute(mlp_tc_kernel,
                             cudaFuncAttributeMaxDynamicSharedMemorySize,
                             SMEM_BYTES);
        configured = 1;
    }

    quant_kernel<<<10, 256>>>(w0, w1, w2, w3, w4, b0, b1, b2, b3, b4);
    grid_kernel<<<(2688 + 255) / 256, 256>>>(ind0, cb0, ind1, cb1, ind2, cb2);
    mlp_tc_kernel<<<592, 128, SMEM_BYTES>>>(x, (float*)d_out, ntiles);
}

// round 7
// speedup vs baseline: 3.7209x; 1.0881x over previous
#include <cuda_runtime.h>
#include <math.h>
#include <stdint.h>

typedef unsigned long long u64;

// ---------------- device-global scratch (no allocs allowed) ----------------
__device__ __align__(16) float  g_w0q[320];      // 5x64 quantized fp32
__device__ __align__(16) float  g_wk[3][4096];   // w1..w3 integer codes 0..63 ([k][j])
__device__ __align__(8)  float  g_qp[3][2];      // {scale, mn} per layer
__device__ __align__(16) float  g_w4q[64];
__device__ __align__(16) float  g_b0q[64];
__device__ __align__(16) float  g_bq[3][64];
__device__ __align__(16) float  g_b4q[4];
__device__ float4 g_grid0[128];
__device__ float4 g_grid1[512];
__device__ float4 g_grid2[2048];

// ---------------- packed helpers -------------------------------------------
__device__ __forceinline__ u64 pack2(float lo, float hi) {
    u64 r;
    asm("mov.b64 %0, {%1, %2};" : "=l"(r) : "f"(lo), "f"(hi));
    return r;
}
__device__ __forceinline__ void unpack2(u64 v, float& lo, float& hi) {
    asm("mov.b64 {%0, %1}, %2;" : "=f"(lo), "=f"(hi) : "l"(v));
}
__device__ __forceinline__ u64 fma2(u64 a, u64 b, u64 c) {
    u64 d;
    asm("fma.rn.f32x2 %0, %1, %2, %3;" : "=l"(d) : "l"(a), "l"(b), "l"(c));
    return d;
}
__device__ __forceinline__ u64 mul2(u64 a, u64 b) {
    u64 d;
    asm("mul.rn.f32x2 %0, %1, %2;" : "=l"(d) : "l"(a), "l"(b));
    return d;
}
__device__ __forceinline__ u64 add2(u64 a, u64 b) {
    u64 d;
    asm("add.rn.f32x2 %0, %1, %2;" : "=l"(d) : "l"(a), "l"(b));
    return d;
}
__device__ __forceinline__ u64 dup2(float c) { return pack2(c, c); }
__device__ __forceinline__ float rcp_fast(float x) {
    float r; asm("rcp.approx.f32 %0, %1;" : "=f"(r) : "f"(x)); return r;
}
__device__ __forceinline__ float ex2_fast(float x) {
    float r; asm("ex2.approx.f32 %0, %1;" : "=f"(r) : "f"(x)); return r;
}
__device__ __forceinline__ u64 rcp2(u64 a) {
    float l, h; unpack2(a, l, h); return pack2(rcp_fast(l), rcp_fast(h));
}
__device__ __forceinline__ u64 ex22(u64 a) {
    float l, h; unpack2(a, l, h); return pack2(ex2_fast(l), ex2_fast(h));
}
__device__ __forceinline__ uint32_t bf16x2_rn(float hi, float lo) {
    uint32_t r;
    asm("cvt.rn.bf16x2.f32 %0, %1, %2;" : "=r"(r) : "f"(hi), "f"(lo));
    return r;   // lo16 = bf16(lo), hi16 = bf16(hi)
}

// packed GELU (A&S 7.1.26, |erf err| <= 1.5e-7)
__device__ __forceinline__ u64 gelu2p(u64 v) {
    const u64 ABS2 = 0x7fffffff7fffffffULL;
    const u64 SGN2 = 0x8000000080000000ULL;
    u64 ONE2 = dup2(1.0f);
    u64 ax = v & ABS2;
    u64 z  = mul2(ax, dup2(0.70710678118654752f));
    u64 t  = rcp2(fma2(z, dup2(0.3275911f), ONE2));
    u64 q  = fma2(dup2(-1.061405429f), t, dup2(1.453152027f));
    q = fma2(q, t, dup2(-1.421413741f));
    q = fma2(q, t, dup2(0.284496736f));
    q = fma2(q, t, dup2(-0.254829592f));
    u64 s  = mul2(q, t);
    u64 z2 = mul2(z, z);
    u64 e  = ex22(mul2(z2, dup2(-1.4426950408889634f)));
    u64 ea = fma2(s, e, ONE2);
    u64 er = ea | (v & SGN2);
    u64 hx = mul2(v, dup2(0.5f));
    return fma2(hx, er, hx);
}

// bf16 tensor-core mma (base PTX, sm_80+): D += A x B
__device__ __forceinline__ void mma_bf16(float d[4], const uint32_t a[4],
                                         uint32_t b0, uint32_t b1) {
    asm volatile(
        "mma.sync.aligned.m16n8k16.row.col.f32.bf16.bf16.f32 "
        "{%0,%1,%2,%3}, {%4,%5,%6,%7}, {%8,%9}, {%0,%1,%2,%3};"
        : "+f"(d[0]), "+f"(d[1]), "+f"(d[2]), "+f"(d[3])
        : "r"(a[0]), "r"(a[1]), "r"(a[2]), "r"(a[3]), "r"(b0), "r"(b1));
}

// ---------------- prep 1: weight quantization (Q_LEVELS = 63) --------------
__global__ void quant_kernel(const float* w0, const float* w1, const float* w2,
                             const float* w3, const float* w4,
                             const float* b0, const float* b1, const float* b2,
                             const float* b3, const float* b4)
{
    __shared__ float smin[256], smax[256];
    const float* src; float* dst; int n; int kcode = 0;
    switch (blockIdx.x) {
        case 0: src = w0; dst = g_w0q;   n = 320;  break;
        case 1: src = w1; dst = g_wk[0]; n = 4096; kcode = 1; break;
        case 2: src = w2; dst = g_wk[1]; n = 4096; kcode = 1; break;
        case 3: src = w3; dst = g_wk[2]; n = 4096; kcode = 1; break;
        case 4: src = w4; dst = g_w4q;   n = 64;   break;
        case 5: src = b0; dst = g_b0q;   n = 64;   break;
        case 6: src = b1; dst = g_bq[0]; n = 64;   break;
        case 7: src = b2; dst = g_bq[1]; n = 64;   break;
        case 8: src = b3; dst = g_bq[2]; n = 64;   break;
        default: src = b4; dst = g_b4q;  n = 1;    break;
    }
    int t = threadIdx.x;
    float mn = INFINITY, mx = -INFINITY;
    for (int i = t; i < n; i += 256) {
        float v = src[i];
        mn = fminf(mn, v); mx = fmaxf(mx, v);
    }
    smin[t] = mn; smax[t] = mx;
    __syncthreads();
    for (int s = 128; s > 0; s >>= 1) {
        if (t < s) {
            smin[t] = fminf(smin[t], smin[t + s]);
            smax[t] = fmaxf(smax[t], smax[t + s]);
        }
        __syncthreads();
    }
    mn = smin[0]; mx = smax[0];
    float scale = fmaxf(mx - mn, 1e-8f) / 63.0f;
    if (kcode) {
        for (int i = t; i < n; i += 256)
            dst[i] = rintf((src[i] - mn) / scale);   // integer code 0..63
        if (t == 0) {
            g_qp[blockIdx.x - 1][0] = scale;
            g_qp[blockIdx.x - 1][1] = mn;
        }
    } else {
        for (int i = t; i < n; i += 256)
            dst[i] = rintf((src[i] - mn) / scale) * scale + mn;
    }
}

// ---------------- prep 2: grid tables (STE forward == argmax gather) --------
__global__ void grid_kernel(const float* ind0, const float* cb0,
                            const float* ind1, const float* cb1,
                            const float* ind2, const float* cb2)
{
    int idx = blockIdx.x * blockDim.x + threadIdx.x;
    const float* ind; const float* cb; float4* dst; int row;
    if (idx < 128)       { ind = ind0; cb = cb0; dst = g_grid0; row = idx; }
    else if (idx < 640)  { ind = ind1; cb = cb1; dst = g_grid1; row = idx - 128; }
    else if (idx < 2688) { ind = ind2; cb = cb2; dst = g_grid2; row = idx - 640; }
    else return;
    const float* r = ind + (long)row * 64;
    float best = r[0]; int arg = 0;
    #pragma unroll
    for (int j = 1; j < 64; j++) {
        float v = r[j];
        if (v > best) { best = v; arg = j; }
    }
    dst[row] = make_float4(cb[arg * 4 + 0], cb[arg * 4 + 1],
                           cb[arg * 4 + 2], cb[arg * 4 + 3]);
}

// ---------------- main tensor-core kernel -----------------------------------
// W_q = scale*K + mn*J with K integer (exact bf16). x@W_q = scale*(x@K) + mn*S,
// S = sum_k x_k (rank-1, computed in registers + 4 shfl). MMA: 2 products
// (a_hi*K + a_lo*K). D-fragment layout == A-fragment layout -> register-resident.
//
// smem (bytes):
//   0     : wf  — B fragments [3l][4kt][8nt][32 lanes] x uint2{b0,b1} = 24576
//   24576 : w0s [320f], 25856: b0s[64f], 26112: bz[3][64f], 26880: w4s[64f],
//   27136 : b4f[4f], 27152: qp[3][2f]+pad, 27184: in5s[5][128f]
#define OFF_WF    0
#define OFF_W0S   24576
#define OFF_B0S   25856
#define OFF_BZ    26112
#define OFF_W4S   26880
#define OFF_B4F   27136
#define OFF_QP    27152
#define OFF_IN5   27184
#define SMEM_BYTES 29744

__global__ void __launch_bounds__(128, 4)
mlp_tc_kernel(const float* __restrict__ x, float* __restrict__ out, int ntiles)
{
    extern __shared__ char smp[];
    const uint2* wf = (const uint2*)(smp + OFF_WF);
    float* w0s = (float*)(smp + OFF_W0S);
    float* b0s = (float*)(smp + OFF_B0S);
    float* bz  = (float*)(smp + OFF_BZ);
    float* w4s = (float*)(smp + OFF_W4S);
    float* b4f = (float*)(smp + OFF_B4F);
    float* qps = (float*)(smp + OFF_QP);
    float* in5s = (float*)(smp + OFF_IN5);

    int t = threadIdx.x;
    int wid = t >> 5;
    int lane = t & 31;
    int g = lane >> 2;      // row group 0..7
    int tig = lane & 3;     // thread-in-group

    // ---- one-time staging ----
    {
        uint2* wfw = (uint2*)(smp + OFF_WF);
        for (int e = t; e < 3072; e += 128) {
            int el = e & 31, nt = (e >> 5) & 7, kt = (e >> 8) & 3, l = e >> 10;
            int eg = el >> 2, etig = el & 3;
            int j = 8 * nt + eg;
            int k0 = 16 * kt + 2 * etig;
            const float* wl = g_wk[l];
            uint32_t b0 = bf16x2_rn(wl[(k0 + 1) * 64 + j], wl[(k0    ) * 64 + j]);
            uint32_t b1 = bf16x2_rn(wl[(k0 + 9) * 64 + j], wl[(k0 + 8) * 64 + j]);
            wfw[e] = make_uint2(b0, b1);   // integers 0..63: exact in bf16
        }
    }
    for (int i = t; i < 320; i += 128) w0s[i] = g_w0q[i];
    if (t < 64) {
        b0s[t] = g_b0q[t];
        bz[t] = g_bq[0][t]; bz[64 + t] = g_bq[1][t]; bz[128 + t] = g_bq[2][t];
        w4s[t] = g_w4q[t];
        if (t == 0) b4f[0] = g_b4q[0];
        if (t < 6) qps[t] = ((const float*)g_qp)[t];
    }

    for (int tile = blockIdx.x; tile < ntiles; tile += gridDim.x) {
        __syncthreads();

        // ---- interp: one point per thread -> in5s[5][128] ----
        int gidx = tile * 128 + t;
        {
            float2 xv = __ldg((const float2*)x + gidx);
            float feat = xv.x;
            float tc = (xv.y + 1.0f) * 0.5f;
            float4 gg = make_float4(0.f, 0.f, 0.f, 0.f);
            auto interp_add = [&](const float4* __restrict__ tab, int res) {
                float c = tc * (float)(res - 1);
                int left  = min((int)floorf(c), res - 2);
                int right = max((int)ceilf(c), 1);
                float w = c - (float)left;
                float4 gl = __ldg(tab + left);
                float4 gr = __ldg(tab + right);
                gg.x += (1.0f - w) * gl.x + w * gr.x;
                gg.y += (1.0f - w) * gl.y + w * gr.y;
                gg.z += (1.0f - w) * gl.z + w * gr.z;
                gg.w += (1.0f - w) * gl.w + w * gr.w;
            };
            interp_add(g_grid0, 128);
            interp_add(g_grid1, 512);
            interp_add(g_grid2, 2048);
            in5s[0 * 128 + t] = gg.x;
            in5s[1 * 128 + t] = gg.y;
            in5s[2 * 128 + t] = gg.z;
            in5s[3 * 128 + t] = gg.w;
            in5s[4 * 128 + t] = feat;
        }
        __syncthreads();

        // ---- each warp: 2 sequential m16 sub-tiles ----
        #pragma unroll 1
        for (int s = 0; s < 2; s++) {
            int mt = wid + 4 * s;
            int poff = mt * 16;

            float d[8][4];
            uint32_t Ahi[4][4], Alo[4][4];
            float Sa = 0.f, Sb = 0.f;   // row sums of current activations

            // ---- layer 0 (5 -> 64) into D layout ----
            {
                float ia[5], ib[5];
                #pragma unroll
                for (int k = 0; k < 5; k++) {
                    ia[k] = in5s[k * 128 + poff + g];
                    ib[k] = in5s[k * 128 + poff + g + 8];
                }
                #pragma unroll
                for (int nt = 0; nt < 8; nt++) {
                    int f0 = 8 * nt + 2 * tig;
                    u64 a0 = pack2(0.f, 0.f), a1 = pack2(0.f, 0.f);
                    #pragma unroll
                    for (int k = 0; k < 5; k++) {
                        u64 wp = *(const u64*)(w0s + k * 64 + f0);
                        a0 = fma2(dup2(ia[k]), wp, a0);
                        a1 = fma2(dup2(ib[k]), wp, a1);
                    }
                    unpack2(a0, d[nt][0], d[nt][1]);
                    unpack2(a1, d[nt][2], d[nt][3]);
                }
            }

            // ---- epilogue: scale*d + bias + off -> gelu -> split + row sums
            auto epi = [&](const float* bias, float scl, float offa, float offb) {
                u64 sa2 = pack2(0.f, 0.f), sb2 = pack2(0.f, 0.f);
                u64 scl2 = dup2(scl);
                #pragma unroll
                for (int nt = 0; nt < 8; nt++) {
                    int f0 = 8 * nt + 2 * tig;
                    u64 bb2 = *(const u64*)(bias + f0);
                    u64 a01 = add2(fma2(scl2, pack2(d[nt][0], d[nt][1]), bb2),
                                   dup2(offa));
                    u64 a23 = add2(fma2(scl2, pack2(d[nt][2], d[nt][3]), bb2),
                                   dup2(offb));
                    u64 p01 = gelu2p(a01);
                    u64 p23 = gelu2p(a23);
                    sa2 = add2(sa2, p01);
                    sb2 = add2(sb2, p23);
                    float g0, g1, g2, g3;
                    unpack2(p01, g0, g1);
                    unpack2(p23, g2, g3);
                    uint32_t h01 = bf16x2_rn(g1, g0);
                    uint32_t h23 = bf16x2_rn(g3, g2);
                    float r0 = __uint_as_float(h01 << 16);
                    float r1 = __uint_as_float(h01 & 0xffff0000u);
                    float r2 = __uint_as_float(h23 << 16);
                    float r3 = __uint_as_float(h23 & 0xffff0000u);
                    uint32_t q01 = bf16x2_rn(g1 - r1, g0 - r0);
                    uint32_t q23 = bf16x2_rn(g3 - r3, g2 - r2);
                    int kt = nt >> 1;
                    int o = (nt & 1) ? 2 : 0;
                    Ahi[kt][o] = h01; Ahi[kt][o + 1] = h23;
                    Alo[kt][o] = q01; Alo[kt][o + 1] = q23;
                }
                float la, ha, lb, hb;
                unpack2(sa2, la, ha); Sa = la + ha;
                unpack2(sb2, lb, hb); Sb = lb + hb;
                Sa += __shfl_xor_sync(0xffffffffu, Sa, 1);
                Sa += __shfl_xor_sync(0xffffffffu, Sa, 2);
                Sb += __shfl_xor_sync(0xffffffffu, Sb, 1);
                Sb += __shfl_xor_sync(0xffffffffu, Sb, 2);
            };
            epi(b0s, 1.0f, 0.f, 0.f);

            // ---- 3 mma layers (2 products each: hi*K + lo*K) ----
            float scl3 = 0.f, offa3 = 0.f, offb3 = 0.f;
            #pragma unroll 1
            for (int l = 0; l < 3; l++) {
                #pragma unroll
                for (int nt = 0; nt < 8; nt++) {
                    d[nt][0] = 0.f; d[nt][1] = 0.f;
                    d[nt][2] = 0.f; d[nt][3] = 0.f;
                }
                const uint2* wfl = wf + (size_t)l * 4 * 8 * 32;
                #pragma unroll
                for (int kt = 0; kt < 4; kt++) {
                    #pragma unroll
                    for (int nt = 0; nt < 8; nt++) {
                        uint2 B = wfl[(kt * 8 + nt) * 32 + lane];
                        mma_bf16(d[nt], Ahi[kt], B.x, B.y);
                        mma_bf16(d[nt], Alo[kt], B.x, B.y);
                    }
                }
                float scl = qps[2 * l], mn = qps[2 * l + 1];
                if (l < 2) epi(bz + 64 * l, scl, mn * Sa, mn * Sb);
                else { scl3 = scl; offa3 = mn * Sa; offb3 = mn * Sb; }
            }

            // ---- final: scale/offset + bias b3, gelu, dot w4, reduce, tanh --
            {
                const float* b3 = bz + 128;
                u64 scl2 = dup2(scl3);
                u64 dg = pack2(0.f, 0.f), dg8 = pack2(0.f, 0.f);
                #pragma unroll
                for (int nt = 0; nt < 8; nt++) {
                    int f0 = 8 * nt + 2 * tig;
                    u64 bb2 = *(const u64*)(b3 + f0);
                    u64 a01 = add2(fma2(scl2, pack2(d[nt][0], d[nt][1]), bb2),
                                   dup2(offa3));
                    u64 a23 = add2(fma2(scl2, pack2(d[nt][2], d[nt][3]), bb2),
                                   dup2(offb3));
                    u64 w4p = *(const u64*)(w4s + f0);
                    dg  = fma2(gelu2p(a01), w4p, dg);
                    dg8 = fma2(gelu2p(a23), w4p, dg8);
                }
                float a, b, sg, sg8;
                unpack2(dg, a, b);  sg  = a + b;
                unpack2(dg8, a, b); sg8 = a + b;
                sg  += __shfl_xor_sync(0xffffffffu, sg, 1);
                sg  += __shfl_xor_sync(0xffffffffu, sg, 2);
                sg8 += __shfl_xor_sync(0xffffffffu, sg8, 1);
                sg8 += __shfl_xor_sync(0xffffffffu, sg8, 2);
                if (tig == 0) {
                    float bb4 = b4f[0];
                    int base = tile * 128 + poff;
                    out[base + g]     = tanhf(sg + bb4);
                    out[base + g + 8] = tanhf(sg8 + bb4);
                }
            }
        }
    }
}

// ---------------- launch ----------------
extern "C" void kernel_launch(void* const* d_in, const int* in_sizes, int n_in,
                              void* d_out, int out_size)
{
    const float* x    = (const float*)d_in[0];
    const float* cb0  = (const float*)d_in[1];
    const float* ind0 = (const float*)d_in[2];
    const float* cb1  = (const float*)d_in[3];
    const float* ind1 = (const float*)d_in[4];
    const float* cb2  = (const float*)d_in[5];
    const float* ind2 = (const float*)d_in[6];
    const float* w0   = (const float*)d_in[7];
    const float* b0   = (const float*)d_in[8];
    const float* w1   = (const float*)d_in[9];
    const float* b1   = (const float*)d_in[10];
    const float* w2   = (const float*)d_in[11];
    const float* b2   = (const float*)d_in[12];
    const float* w3   = (const float*)d_in[13];
    const float* b3   = (const float*)d_in[14];
    const float* w4   = (const float*)d_in[15];
    const float* b4   = (const float*)d_in[16];

    int N = in_sizes[0] / 2;
    int ntiles = N / 128;

    static int configured = 0;
    if (!configured) {
        cudaFuncSetAttribute(mlp_tc_kernel,
                             cudaFuncAttributeMaxDynamicSharedMemorySize,
                             SMEM_BYTES);
        configured = 1;
    }

    quant_kernel<<<10, 256>>>(w0, w1, w2, w3, w4, b0, b1, b2, b3, b4);
    grid_kernel<<<(2688 + 255) / 256, 256>>>(ind0, cb0, ind1, cb1, ind2, cb2);
    mlp_tc_kernel<<<592, 128, SMEM_BYTES>>>(x, (float*)d_out, ntiles);
}